// round 14
// baseline (speedup 1.0000x reference)
#include <cuda_runtime.h>
#include <cstdint>

// QuantumEvolution: B=512 x M=2048. SU(2) step propagators = unit quaternions.
// R14: TPB=128, 16 steps/thread (halves per-SM scan/shuffle overhead at fixed
// total work; R5/R4 trend says scan SHFL/SM tracks duration). Dual packed
// half-chains (steps i | i+8), warp scan + tiny 4-entry cross-warp scan,
// 1 block barrier, warp-local staged copy-out.

#define TPB    128
#define MSTEPS 2048
#define BREAL  512

#define ROW_F4     25                 // 24 data f4 + 1 pad (odd -> conflict-free)
#define SMEM_BYTES (TPB * ROW_F4 * 16)   // 51200 B

typedef unsigned long long u64;

// ---- packed f32x2 helpers (sm_103a FFMA2 path) ----
__device__ __forceinline__ u64 f2pack(float lo, float hi) {
    u64 d;
    asm("mov.b64 %0, {%1, %2};" : "=l"(d)
        : "r"(__float_as_uint(lo)), "r"(__float_as_uint(hi)));
    return d;
}
__device__ __forceinline__ void f2unpack(float& lo, float& hi, u64 s) {
    unsigned a, b;
    asm("mov.b64 {%0, %1}, %2;" : "=r"(a), "=r"(b) : "l"(s));
    lo = __uint_as_float(a); hi = __uint_as_float(b);
}
__device__ __forceinline__ u64 f2mul(u64 a, u64 b) {
    u64 d; asm("mul.rn.f32x2 %0, %1, %2;" : "=l"(d) : "l"(a), "l"(b)); return d;
}
__device__ __forceinline__ u64 f2fma(u64 a, u64 b, u64 c) {
    u64 d; asm("fma.rn.f32x2 %0, %1, %2, %3;" : "=l"(d) : "l"(a), "l"(b), "l"(c)); return d;
}
__device__ __forceinline__ u64 f2add(u64 a, u64 b) {
    u64 d; asm("add.rn.f32x2 %0, %1, %2;" : "=l"(d) : "l"(a), "l"(b)); return d;
}
__device__ __forceinline__ u64 f2neg(u64 a) {
    u64 d; asm("xor.b64 %0, %1, 0x8000000080000000;" : "=l"(d) : "l"(a)); return d;
}

__device__ __forceinline__ float4 qmul(float4 a, float4 b) {
    // Hamilton product a*b; quaternion (w,x,y,z) in (x,y,z,w) fields.
    float4 r;
    r.x = a.x * b.x - a.y * b.y - a.z * b.z - a.w * b.w;
    r.y = a.x * b.y + a.y * b.x + a.z * b.w - a.w * b.z;
    r.z = a.x * b.z - a.y * b.w + a.z * b.x + a.w * b.y;
    r.w = a.x * b.w + a.y * b.z - a.z * b.y + a.w * b.x;
    return r;
}

__device__ __forceinline__ float4 shfl_up_q(float4 v, int off) {
    float4 r;
    r.x = __shfl_up_sync(0xFFFFFFFFu, v.x, off);
    r.y = __shfl_up_sync(0xFFFFFFFFu, v.y, off);
    r.z = __shfl_up_sync(0xFFFFFFFFu, v.z, off);
    r.w = __shfl_up_sync(0xFFFFFFFFu, v.w, off);
    return r;
}

__device__ __forceinline__ float4 shfl_q(float4 v, int src) {
    float4 r;
    r.x = __shfl_sync(0xFFFFFFFFu, v.x, src);
    r.y = __shfl_sync(0xFFFFFFFFu, v.y, src);
    r.z = __shfl_sync(0xFFFFFFFFu, v.z, src);
    r.w = __shfl_sync(0xFFFFFFFFu, v.w, src);
    return r;
}

// Packed step quaternion for two independent steps (lo|hi lanes).
__device__ __forceinline__ void stepq2(u64 hx, u64 hy, u64 hz,
                                       u64& uw, u64& ux, u64& uy, u64& uz) {
    const float dt = 1.0f / 2048.0f;
    const u64 DT2  = f2pack(dt * dt, dt * dt);
    const u64 DT   = f2pack(dt, dt);
    const u64 ONE  = f2pack(1.f, 1.f);
    const u64 CN05 = f2pack(-0.5f, -0.5f);
    const u64 CN16 = f2pack(-1.f / 6.f, -1.f / 6.f);
    u64 m  = f2fma(hz, hz, f2fma(hy, hy, f2mul(hx, hx)));
    u64 t2 = f2mul(DT2, m);
    uw = f2fma(t2, CN05, ONE);                       // cos(theta)
    u64 k = f2mul(DT, f2fma(t2, CN16, ONE));         // dt*sinc(theta)
    ux = f2mul(k, hx); uy = f2mul(k, hy); uz = f2mul(k, hz);
}

// Packed Hamilton product r = u * b (u's vector negations supplied).
__device__ __forceinline__ void qmul2_negA(
    u64 aw, u64 ax, u64 ay, u64 az, u64 nax, u64 nay, u64 naz,
    u64 bw, u64 bx, u64 by, u64 bz,
    u64& rw, u64& rx, u64& ry, u64& rz) {
    rw = f2fma(naz, bz, f2fma(nay, by, f2fma(nax, bx, f2mul(aw, bw))));
    rx = f2fma(ay,  bz, f2fma(naz, by, f2fma(aw,  bx, f2mul(ax, bw))));
    ry = f2fma(az,  bx, f2fma(nax, bz, f2fma(aw,  by, f2mul(ay, bw))));
    rz = f2fma(ax,  by, f2fma(nay, bx, f2fma(aw,  bz, f2mul(az, bw))));
}

__global__ __launch_bounds__(TPB, 4)
void qe_kernel(const float* __restrict__ noise,
               const float* __restrict__ pulses,
               float* __restrict__ out) {
    extern __shared__ float4 sm4[];
    __shared__ float4 wtot[TPB / 32];

    const int b    = blockIdx.x;
    const int tid  = threadIdx.x;
    const int lane = tid & 31;
    const int wid  = tid >> 5;

    // ---- Loads: thread t owns steps 16t..16t+15 (noise first) ----
    const float4* gn = reinterpret_cast<const float4*>(noise  + (size_t)b * MSTEPS)     + 4 * tid;
    const float4* gp = reinterpret_cast<const float4*>(pulses + (size_t)b * MSTEPS * 2) + 8 * tid;
    float Nf[16], Pf[32];
#pragma unroll
    for (int j = 0; j < 4; j++) {
        float4 v = gn[j];
        Nf[4*j] = v.x; Nf[4*j+1] = v.y; Nf[4*j+2] = v.z; Nf[4*j+3] = v.w;
    }
#pragma unroll
    for (int j = 0; j < 8; j++) {
        float4 v = gp[j];
        Pf[4*j] = v.x; Pf[4*j+1] = v.y; Pf[4*j+2] = v.z; Pf[4*j+3] = v.w;
    }

    // ---- Dual packed half-chains: lane0 = steps 0..7, lane1 = steps 8..15 ----
    const u64 H05 = f2pack(0.5f, 0.5f);
    u64 Cw[8], Cx[8], Cy[8], Cz[8];    // C2[i] = (L[i] | Hi[i])
#pragma unroll
    for (int i = 0; i < 8; i++) {
        // step i uses pulses floats (2i, 2i+1); step 8+i uses (16+2i, 17+2i).
        u64 hx = f2pack(Pf[2*i],   Pf[16+2*i]);
        u64 hy = f2pack(Pf[2*i+1], Pf[17+2*i]);
        u64 hz = f2add(f2pack(Nf[i], Nf[8+i]), H05);
        if (i == 0) {
            stepq2(hx, hy, hz, Cw[0], Cx[0], Cy[0], Cz[0]);
        } else {
            u64 uw, ux, uy, uz;
            stepq2(hx, hy, hz, uw, ux, uy, uz);
            qmul2_negA(uw, ux, uy, uz, f2neg(ux), f2neg(uy), f2neg(uz),
                       Cw[i-1], Cx[i-1], Cy[i-1], Cz[i-1],
                       Cw[i],   Cx[i],   Cy[i],   Cz[i]);
        }
    }

    // ---- L7 (steps 0..7 product) and Hi7 (8..15); chunk total = Hi7*L7 ----
    float4 L7q, Hi7;
    f2unpack(L7q.x, Hi7.x, Cw[7]); f2unpack(L7q.y, Hi7.y, Cx[7]);
    f2unpack(L7q.z, Hi7.z, Cy[7]); f2unpack(L7q.w, Hi7.w, Cz[7]);

    // ---- Warp-level inclusive scan of chunk products ----
    float4 v = qmul(Hi7, L7q);
#pragma unroll
    for (int off = 1; off < 32; off <<= 1) {
        float4 o = shfl_up_q(v, off);
        if (lane >= off) v = qmul(v, o);
    }
    if (lane == 31) wtot[wid] = v;
    __syncthreads();                 // the ONLY block barrier

    // ---- Every warp redundantly scans the 4 warp totals (2 rounds) ----
    float4 t = wtot[lane & 3];
#pragma unroll
    for (int off = 1; off < 4; off <<= 1) {
        float4 o = shfl_up_q(t, off);
        if (lane >= off && lane < 4) t = qmul(t, o);
    }
    float4 WE = shfl_q(t, (wid > 0) ? (wid - 1) : 0);
    if (wid == 0) WE = make_float4(1.f, 0.f, 0.f, 0.f);

    float4 TE = shfl_up_q(v, 1);
    if (lane == 0) TE = make_float4(1.f, 0.f, 0.f, 0.f);
    const float4 E = qmul(TE, WE);   // exclusive prefix for this 16-step chunk
    const float4 F = qmul(L7q, E);   // prefix for the hi half (steps 8..15)

    // ---- Packed epilogue: P2(i) = C2[i]*(E|F); lane0->step i, lane1->i+8 ----
    const u64 Bw  = f2pack(E.x, F.x), Bx = f2pack(E.y, F.y);
    const u64 By  = f2pack(E.z, F.z), Bz = f2pack(E.w, F.w);
    const u64 nBx = f2neg(Bx), nBy = f2neg(By), nBz = f2neg(Bz);
    const u64 M2  = f2pack(-2.f, -2.f), ONE = f2pack(1.f, 1.f);

    float4* srow = &sm4[tid * ROW_F4];
#pragma unroll
    for (int g = 0; g < 4; g++) {    // composes i=2g, 2g+1 together
        u64 S[2][6];
#pragma unroll
        for (int h = 0; h < 2; h++) {
            const int i = 2 * g + h;
            const u64 aw = Cw[i], ax = Cx[i], ay = Cy[i], az = Cz[i];
            u64 Pw = f2fma(az, nBz, f2fma(ay, nBy, f2fma(ax, nBx, f2mul(aw, Bw))));
            u64 Px = f2fma(az, nBy, f2fma(ay,  Bz, f2fma(ax,  Bw, f2mul(aw, Bx))));
            u64 Py = f2fma(az,  Bx, f2fma(ay,  Bw, f2fma(ax, nBz, f2mul(aw, By))));
            u64 Pz = f2fma(az,  Bw, f2fma(ay, nBx, f2fma(ax,  By, f2mul(aw, Bz))));
            u64 nPw = f2neg(Pw);
            u64 xz  = f2mul(Px, Pz);
            u64 s0  = f2fma(Pw, Py, xz);  s0 = f2add(s0, s0);
            u64 s1  = f2fma(nPw, Px, f2mul(Py, Pz)); s1 = f2add(s1, s1);
            u64 s2  = f2fma(f2fma(Py, Py, f2mul(Px, Px)), M2, ONE);
            u64 s3  = f2fma(f2fma(Pz, Pz, f2mul(Py, Py)), M2, ONE);
            u64 s4  = f2fma(Pw, Pz, f2mul(Px, Py)); s4 = f2add(s4, s4);
            u64 s5  = f2fma(nPw, Py, xz); s5 = f2add(s5, s5);
            S[h][0] = s0; S[h][1] = s1; S[h][2] = s2;
            S[h][3] = s3; S[h][4] = s4; S[h][5] = s5;
        }
        float a0,b0,a1,b1,a2,b2,a3,b3,a4,b4,a5,b5;
        float c0,d0,c1,d1,c2,d2,c3,d3,c4,d4,c5,d5;
        f2unpack(a0,b0,S[0][0]); f2unpack(a1,b1,S[0][1]); f2unpack(a2,b2,S[0][2]);
        f2unpack(a3,b3,S[0][3]); f2unpack(a4,b4,S[0][4]); f2unpack(a5,b5,S[0][5]);
        f2unpack(c0,d0,S[1][0]); f2unpack(c1,d1,S[1][1]); f2unpack(c2,d2,S[1][2]);
        f2unpack(c3,d3,S[1][3]); f2unpack(c4,d4,S[1][4]); f2unpack(c5,d5,S[1][5]);
        // steps (2g,2g+1) -> f4 [3g,3g+3); steps (2g+8,2g+9) -> f4 [3g+12,3g+15)
        srow[3 * g + 0]  = make_float4(a0, a1, a2, a3);
        srow[3 * g + 1]  = make_float4(a4, a5, c0, c1);
        srow[3 * g + 2]  = make_float4(c2, c3, c4, c5);
        srow[3 * g + 12] = make_float4(b0, b1, b2, b3);
        srow[3 * g + 13] = make_float4(b4, b5, d0, d1);
        srow[3 * g + 14] = make_float4(d2, d3, d4, d5);
    }
    __syncwarp();                    // producer = consumer = this warp

    // ---- Warp-local coalesced copy-out: warp w owns rows [32w, 32w+32) ----
    // 32 rows x 24 f4 = 768 f4 per warp; lane handles g = lane + 32k, k<24.
    float4* og = reinterpret_cast<float4*>(out + (size_t)b * (MSTEPS * 6)) + 768 * wid;
    int r = (lane >= 24) ? 1 : 0;
    int c = lane - 24 * r;
    r += 32 * wid;
#pragma unroll
    for (int k = 0; k < 24; k++) {
        og[lane + 32 * k] = sm4[r * ROW_F4 + c];
        r += 1; c += 8;              // +32 f4 = +1 row +8 cols
        if (c >= 24) { c -= 24; r += 1; }
    }
}

extern "C" void kernel_launch(void* const* d_in, const int* in_sizes, int n_in,
                              void* d_out, int out_size) {
    const float* noise  = (const float*)d_in[0];   // [512, 2048, 1]
    const float* pulses = (const float*)d_in[1];   // [512, 2048, 2]
    if (in_sizes[0] > in_sizes[1]) {               // defensive: order by size
        const float* t = noise; noise = pulses; pulses = t;
    }
    cudaFuncSetAttribute(qe_kernel,
                         cudaFuncAttributeMaxDynamicSharedMemorySize,
                         SMEM_BYTES);
    qe_kernel<<<BREAL, TPB, SMEM_BYTES>>>(noise, pulses, (float*)d_out);
}

// round 16
// speedup vs baseline: 1.1775x; 1.1775x over previous
#include <cuda_runtime.h>
#include <cstdint>

// QuantumEvolution: B=512 x M=2048. SU(2) step propagators = unit quaternions.
// R16 = R15 with the divergent-shuffle deadlock fixed: the block total BT is
// computed by ALL threads (uniform shfl), and only the DSMEM store+arrive is
// divergent. 2-CTA cluster per trajectory (grid=1024, TPB=128) removes the
// 16% wave-quantization tax of grid=512 (max 7 vs mean 6.92 CTAs/SM).

#define TPB    128
#define STEPS  8
#define MSTEPS 2048
#define HSTEPS 1024

#define SM_F4      (TPB * 13)          // stage rows: 13 f4 (48 fl + 16B pad)
#define SMEM_BYTES (SM_F4 * 16)        // 26624 B dynamic

typedef unsigned long long u64;

// ---- packed f32x2 helpers (sm_103a FFMA2 path) ----
__device__ __forceinline__ u64 f2pack(float lo, float hi) {
    u64 d;
    asm("mov.b64 %0, {%1, %2};" : "=l"(d)
        : "r"(__float_as_uint(lo)), "r"(__float_as_uint(hi)));
    return d;
}
__device__ __forceinline__ void f2unpack(float& lo, float& hi, u64 s) {
    unsigned a, b;
    asm("mov.b64 {%0, %1}, %2;" : "=r"(a), "=r"(b) : "l"(s));
    lo = __uint_as_float(a); hi = __uint_as_float(b);
}
__device__ __forceinline__ u64 f2mul(u64 a, u64 b) {
    u64 d; asm("mul.rn.f32x2 %0, %1, %2;" : "=l"(d) : "l"(a), "l"(b)); return d;
}
__device__ __forceinline__ u64 f2fma(u64 a, u64 b, u64 c) {
    u64 d; asm("fma.rn.f32x2 %0, %1, %2, %3;" : "=l"(d) : "l"(a), "l"(b), "l"(c)); return d;
}
__device__ __forceinline__ u64 f2add(u64 a, u64 b) {
    u64 d; asm("add.rn.f32x2 %0, %1, %2;" : "=l"(d) : "l"(a), "l"(b)); return d;
}
__device__ __forceinline__ u64 f2neg(u64 a) {
    u64 d; asm("xor.b64 %0, %1, 0x8000000080000000;" : "=l"(d) : "l"(a)); return d;
}

__device__ __forceinline__ float4 qmul(float4 a, float4 b) {
    // Hamilton product a*b; quaternion (w,x,y,z) in (x,y,z,w) fields.
    float4 r;
    r.x = a.x * b.x - a.y * b.y - a.z * b.z - a.w * b.w;
    r.y = a.x * b.y + a.y * b.x + a.z * b.w - a.w * b.z;
    r.z = a.x * b.z - a.y * b.w + a.z * b.x + a.w * b.y;
    r.w = a.x * b.w + a.y * b.z - a.z * b.y + a.w * b.x;
    return r;
}

__device__ __forceinline__ float4 shfl_up_q(float4 v, int off) {
    float4 r;
    r.x = __shfl_up_sync(0xFFFFFFFFu, v.x, off);
    r.y = __shfl_up_sync(0xFFFFFFFFu, v.y, off);
    r.z = __shfl_up_sync(0xFFFFFFFFu, v.z, off);
    r.w = __shfl_up_sync(0xFFFFFFFFu, v.w, off);
    return r;
}

__device__ __forceinline__ float4 shfl_q(float4 v, int src) {
    float4 r;
    r.x = __shfl_sync(0xFFFFFFFFu, v.x, src);
    r.y = __shfl_sync(0xFFFFFFFFu, v.y, src);
    r.z = __shfl_sync(0xFFFFFFFFu, v.z, src);
    r.w = __shfl_sync(0xFFFFFFFFu, v.w, src);
    return r;
}

__device__ __forceinline__ float4 stepq(float hx, float hy, float hz) {
    const float dt = 1.0f / 2048.0f;
    float t2 = (dt * dt) * (hx * hx + hy * hy + hz * hz);   // theta^2 <= ~1.5e-5
    float c = 1.f - 0.5f * t2;                              // cos(theta)
    float k = dt * (1.f - t2 * (1.f / 6.f));                // dt*sinc(theta)
    return make_float4(c, k * hx, k * hy, k * hz);
}

__global__ __launch_bounds__(TPB, 7) __cluster_dims__(2, 1, 1)
void qe_kernel(const float* __restrict__ noise,
               const float* __restrict__ pulses,
               float* __restrict__ out) {
    extern __shared__ float4 sm4[];
    __shared__ float4 wtot[TPB / 32];
    __shared__ float4 t0slot;               // rank1: receives rank0's total
    __shared__ u64 mbar;                    // 8B mbarrier

    const int tid  = threadIdx.x;
    const int lane = tid & 31;
    const int wid  = tid >> 5;
    const unsigned rank = blockIdx.x & 1;   // half of the trajectory
    const int b = blockIdx.x >> 1;          // trajectory index

    const unsigned mbar_sa = (unsigned)__cvta_generic_to_shared(&mbar);
    const unsigned t0_sa   = (unsigned)__cvta_generic_to_shared(&t0slot);

    if (tid == 0) {
        asm volatile("mbarrier.init.shared.b64 [%0], 1;"
                     :: "r"(mbar_sa) : "memory");
    }
    // All cluster mbarriers visible before any remote arrive.
    asm volatile("barrier.cluster.arrive.aligned;" ::: "memory");
    asm volatile("barrier.cluster.wait.aligned;" ::: "memory");

    // ---- Loads: this CTA owns steps [rank*1024, rank*1024+1024) ----
    const float4* gn = reinterpret_cast<const float4*>(noise)
                     + (size_t)b * (MSTEPS / 4) + rank * (HSTEPS / 4) + 2 * tid;
    const float4* gp = reinterpret_cast<const float4*>(pulses)
                     + (size_t)b * (MSTEPS / 2) + rank * (HSTEPS / 2) + 4 * tid;
    const float4 na = gn[0], nb = gn[1];
    const float4 pa = gp[0], pb = gp[1], pc = gp[2], pd = gp[3];

    // ---- Local inclusive prefixes L[8] (newer step on the left) ----
    float4 L[STEPS];
    L[0] = stepq(pa.x, pa.y, 0.5f + na.x);
    L[1] = qmul(stepq(pa.z, pa.w, 0.5f + na.y), L[0]);
    L[2] = qmul(stepq(pb.x, pb.y, 0.5f + na.z), L[1]);
    L[3] = qmul(stepq(pb.z, pb.w, 0.5f + na.w), L[2]);
    L[4] = qmul(stepq(pc.x, pc.y, 0.5f + nb.x), L[3]);
    L[5] = qmul(stepq(pc.z, pc.w, 0.5f + nb.y), L[4]);
    L[6] = qmul(stepq(pd.x, pd.y, 0.5f + nb.z), L[5]);
    L[7] = qmul(stepq(pd.z, pd.w, 0.5f + nb.w), L[6]);

    // ---- Warp-level inclusive scan of chunk products ----
    float4 v = L[7];
#pragma unroll
    for (int off = 1; off < 32; off <<= 1) {
        float4 o = shfl_up_q(v, off);
        if (lane >= off) v = qmul(v, o);
    }
    if (lane == 31) wtot[wid] = v;
    __syncthreads();

    // ---- Every warp redundantly scans the 4 warp totals (2 rounds) ----
    float4 t = wtot[lane & 3];
#pragma unroll
    for (int off = 1; off < 4; off <<= 1) {
        float4 o = shfl_up_q(t, off);
        if (lane >= off && lane < 4) t = qmul(t, o);
    }

    // Block total: UNIFORM shuffle, executed by every thread (fixes the
    // R15 deadlock: no shfl inside divergent control flow).
    const float4 BT = shfl_q(t, 3);

    // Rank 0, thread 0: push BT into rank 1's smem, then release-arrive.
    if (rank == 0 && tid == 0) {
        unsigned r_t0, r_mb;
        asm("mapa.shared::cluster.u32 %0, %1, 1;" : "=r"(r_t0) : "r"(t0_sa));
        asm("mapa.shared::cluster.u32 %0, %1, 1;" : "=r"(r_mb) : "r"(mbar_sa));
        u64 lo = f2pack(BT.x, BT.y), hi = f2pack(BT.z, BT.w);
        asm volatile("st.shared::cluster.b64 [%0], %1;"   :: "r"(r_t0), "l"(lo) : "memory");
        asm volatile("st.shared::cluster.b64 [%0+8], %1;" :: "r"(r_t0), "l"(hi) : "memory");
        asm volatile("mbarrier.arrive.release.cluster.shared::cluster.b64 _, [%0];"
                     :: "r"(r_mb) : "memory");
    }

    float4 WE = shfl_q(t, (wid > 0) ? (wid - 1) : 0);
    if (wid == 0) WE = make_float4(1.f, 0.f, 0.f, 0.f);
    float4 TE = shfl_up_q(v, 1);
    if (lane == 0) TE = make_float4(1.f, 0.f, 0.f, 0.f);
    float4 E = qmul(TE, WE);         // exclusive prefix within this half

    // Rank 1: fold in the first-half total (arrives via DSMEM).
    if (rank == 1) {
        unsigned done;
        asm volatile(
            "{\n\t.reg .pred p;\n\t"
            "WAITLP_%=:\n\t"
            "mbarrier.try_wait.parity.acquire.cluster.shared::cta.b64 p, [%1], 0, 0x989680;\n\t"
            "@p bra.uni WAITDN_%=;\n\t"
            "bra.uni WAITLP_%=;\n\t"
            "WAITDN_%=:\n\t"
            "mov.u32 %0, 1;\n\t}"
            : "=r"(done) : "r"(mbar_sa) : "memory");
        E = qmul(E, t0slot);
    }

    // ---- Packed-f32x2 epilogue -> stage rows (13 f4, pad) ----
    const u64 Ew  = f2pack(E.x, E.x), Ex  = f2pack(E.y, E.y);
    const u64 Ey  = f2pack(E.z, E.z), Ez  = f2pack(E.w, E.w);
    const u64 nEx = f2neg(Ex), nEy = f2neg(Ey), nEz = f2neg(Ez);
    const u64 M2  = f2pack(-2.f, -2.f), ONE = f2pack(1.f, 1.f);

    float4* srow = &sm4[tid * 13];
#pragma unroll
    for (int j = 0; j < 4; j++) {
        const float4 A = L[2 * j], Bq = L[2 * j + 1];
        const u64 aw = f2pack(A.x, Bq.x), ax = f2pack(A.y, Bq.y);
        const u64 ay = f2pack(A.z, Bq.z), az = f2pack(A.w, Bq.w);
        u64 Pw = f2fma(az, nEz, f2fma(ay, nEy, f2fma(ax, nEx, f2mul(aw, Ew))));
        u64 Px = f2fma(az, nEy, f2fma(ay,  Ez, f2fma(ax,  Ew, f2mul(aw, Ex))));
        u64 Py = f2fma(az,  Ex, f2fma(ay,  Ew, f2fma(ax, nEz, f2mul(aw, Ey))));
        u64 Pz = f2fma(az,  Ew, f2fma(ay, nEx, f2fma(ax,  Ey, f2mul(aw, Ez))));
        u64 nPw = f2neg(Pw);
        u64 xz  = f2mul(Px, Pz);
        u64 s0  = f2fma(Pw, Py, xz);  s0 = f2add(s0, s0);            // 2(xz+wy)
        u64 s1  = f2fma(nPw, Px, f2mul(Py, Pz)); s1 = f2add(s1, s1); // 2(yz-wx)
        u64 s2  = f2fma(f2fma(Py, Py, f2mul(Px, Px)), M2, ONE);      // 1-2(xx+yy)
        u64 s3  = f2fma(f2fma(Pz, Pz, f2mul(Py, Py)), M2, ONE);      // 1-2(yy+zz)
        u64 s4  = f2fma(Pw, Pz, f2mul(Px, Py)); s4 = f2add(s4, s4);  // 2(xy+wz)
        u64 s5  = f2fma(nPw, Py, xz); s5 = f2add(s5, s5);            // 2(xz-wy)
        float a0, b0, a1, b1, a2, b2, a3, b3, a4, b4, a5, b5;
        f2unpack(a0, b0, s0); f2unpack(a1, b1, s1); f2unpack(a2, b2, s2);
        f2unpack(a3, b3, s3); f2unpack(a4, b4, s4); f2unpack(a5, b5, s5);
        srow[j * 3 + 0] = make_float4(a0, a1, a2, a3);
        srow[j * 3 + 1] = make_float4(a4, a5, b0, b1);
        srow[j * 3 + 2] = make_float4(b2, b3, b4, b5);
    }
    __syncwarp();                    // producer = consumer = this warp

    // ---- Warp-local coalesced copy-out: warp wid owns rows [32w, 32w+32) ----
    float4* og = reinterpret_cast<float4*>(out)
               + (size_t)b * 3072 + rank * 1536 + 384 * wid;
    int r = lane / 12 + 32 * wid;
    int c = lane - (lane / 12) * 12;
#pragma unroll
    for (int k = 0; k < 12; k++) {
        og[lane + 32 * k] = sm4[r * 13 + c];
        r += 2; c += 8;              // advance by 32 f4 = 2 rows + 8 cols
        if (c >= 12) { c -= 12; r += 1; }
    }

    // No CTA may exit while a peer op targeting its smem may be in flight.
    asm volatile("barrier.cluster.arrive.aligned;" ::: "memory");
    asm volatile("barrier.cluster.wait.aligned;" ::: "memory");
}

extern "C" void kernel_launch(void* const* d_in, const int* in_sizes, int n_in,
                              void* d_out, int out_size) {
    const float* noise  = (const float*)d_in[0];   // [512, 2048, 1]
    const float* pulses = (const float*)d_in[1];   // [512, 2048, 2]
    if (in_sizes[0] > in_sizes[1]) {               // defensive: order by size
        const float* t = noise; noise = pulses; pulses = t;
    }
    qe_kernel<<<1024, TPB, SMEM_BYTES>>>(noise, pulses, (float*)d_out);
}

// round 17
// speedup vs baseline: 1.1805x; 1.0025x over previous
#include <cuda_runtime.h>
#include <cstdint>

// QuantumEvolution: B=512 x M=2048. SU(2) step propagators = unit quaternions;
// prefix product via warp shuffle scan. R17 = R13 (proven optimum, 12.77us):
// dual packed f32x2 half-chains (steps i | i+4 per lane), warp scan + 3-round
// redundant cross-warp scan, 1 block barrier, warp-local staged copy-out.
// New: evict-first (.cs) output stores so the 25MB write stream stops
// thrashing the L2 ways holding the replayed input stream.

#define TPB    256
#define MSTEPS 2048
#define BREAL  512

#define SM_F4      (256 * 13)        // stage rows: 13 f4 (48 fl + 16B pad)
#define SMEM_BYTES (SM_F4 * 16)

typedef unsigned long long u64;

// ---- packed f32x2 helpers (sm_103a FFMA2 path) ----
__device__ __forceinline__ u64 f2pack(float lo, float hi) {
    u64 d;
    asm("mov.b64 %0, {%1, %2};" : "=l"(d)
        : "r"(__float_as_uint(lo)), "r"(__float_as_uint(hi)));
    return d;
}
__device__ __forceinline__ void f2unpack(float& lo, float& hi, u64 s) {
    unsigned a, b;
    asm("mov.b64 {%0, %1}, %2;" : "=r"(a), "=r"(b) : "l"(s));
    lo = __uint_as_float(a); hi = __uint_as_float(b);
}
__device__ __forceinline__ u64 f2mul(u64 a, u64 b) {
    u64 d; asm("mul.rn.f32x2 %0, %1, %2;" : "=l"(d) : "l"(a), "l"(b)); return d;
}
__device__ __forceinline__ u64 f2fma(u64 a, u64 b, u64 c) {
    u64 d; asm("fma.rn.f32x2 %0, %1, %2, %3;" : "=l"(d) : "l"(a), "l"(b), "l"(c)); return d;
}
__device__ __forceinline__ u64 f2add(u64 a, u64 b) {
    u64 d; asm("add.rn.f32x2 %0, %1, %2;" : "=l"(d) : "l"(a), "l"(b)); return d;
}
__device__ __forceinline__ u64 f2neg(u64 a) {
    u64 d; asm("xor.b64 %0, %1, 0x8000000080000000;" : "=l"(d) : "l"(a)); return d;
}

__device__ __forceinline__ float4 qmul(float4 a, float4 b) {
    // Hamilton product a*b; quaternion (w,x,y,z) in (x,y,z,w) fields.
    float4 r;
    r.x = a.x * b.x - a.y * b.y - a.z * b.z - a.w * b.w;
    r.y = a.x * b.y + a.y * b.x + a.z * b.w - a.w * b.z;
    r.z = a.x * b.z - a.y * b.w + a.z * b.x + a.w * b.y;
    r.w = a.x * b.w + a.y * b.z - a.z * b.y + a.w * b.x;
    return r;
}

__device__ __forceinline__ float4 shfl_up_q(float4 v, int off) {
    float4 r;
    r.x = __shfl_up_sync(0xFFFFFFFFu, v.x, off);
    r.y = __shfl_up_sync(0xFFFFFFFFu, v.y, off);
    r.z = __shfl_up_sync(0xFFFFFFFFu, v.z, off);
    r.w = __shfl_up_sync(0xFFFFFFFFu, v.w, off);
    return r;
}

__device__ __forceinline__ float4 shfl_q(float4 v, int src) {
    float4 r;
    r.x = __shfl_sync(0xFFFFFFFFu, v.x, src);
    r.y = __shfl_sync(0xFFFFFFFFu, v.y, src);
    r.z = __shfl_sync(0xFFFFFFFFu, v.z, src);
    r.w = __shfl_sync(0xFFFFFFFFu, v.w, src);
    return r;
}

// Packed step quaternion for two independent steps (lo|hi lanes).
// theta^2 <= ~1.5e-5 -> 1st-order terms suffice (err ~1e-11 << 1e-3).
__device__ __forceinline__ void stepq2(u64 hx, u64 hy, u64 hz,
                                       u64& uw, u64& ux, u64& uy, u64& uz) {
    const float dt = 1.0f / 2048.0f;
    const u64 DT2  = f2pack(dt * dt, dt * dt);
    const u64 DT   = f2pack(dt, dt);
    const u64 ONE  = f2pack(1.f, 1.f);
    const u64 CN05 = f2pack(-0.5f, -0.5f);
    const u64 CN16 = f2pack(-1.f / 6.f, -1.f / 6.f);
    u64 m  = f2fma(hz, hz, f2fma(hy, hy, f2mul(hx, hx)));
    u64 t2 = f2mul(DT2, m);
    uw = f2fma(t2, CN05, ONE);                       // cos(theta)
    u64 k = f2mul(DT, f2fma(t2, CN16, ONE));         // dt*sinc(theta)
    ux = f2mul(k, hx); uy = f2mul(k, hy); uz = f2mul(k, hz);
}

// Packed Hamilton product r = a*b with a's vector negations supplied.
__device__ __forceinline__ void qmul2_negA(
    u64 aw, u64 ax, u64 ay, u64 az, u64 nax, u64 nay, u64 naz,
    u64 bw, u64 bx, u64 by, u64 bz,
    u64& rw, u64& rx, u64& ry, u64& rz) {
    rw = f2fma(naz, bz, f2fma(nay, by, f2fma(nax, bx, f2mul(aw, bw))));
    rx = f2fma(ay,  bz, f2fma(naz, by, f2fma(aw,  bx, f2mul(ax, bw))));
    ry = f2fma(az,  bx, f2fma(nax, bz, f2fma(aw,  by, f2mul(ay, bw))));
    rz = f2fma(ax,  by, f2fma(nay, bx, f2fma(aw,  bz, f2mul(az, bw))));
}

// Evict-first float4 global store.
__device__ __forceinline__ void stg_cs(float4* p, float4 v) {
    asm volatile("st.global.cs.v4.f32 [%0], {%1, %2, %3, %4};"
                 :: "l"(p), "f"(v.x), "f"(v.y), "f"(v.z), "f"(v.w)
                 : "memory");
}

__global__ __launch_bounds__(TPB, 4)
void qe_kernel(const float* __restrict__ noise,
               const float* __restrict__ pulses,
               float* __restrict__ out) {
    extern __shared__ float4 sm4[];
    __shared__ float4 wtot[TPB / 32];

    const int b    = blockIdx.x;
    const int tid  = threadIdx.x;
    const int lane = tid & 31;
    const int wid  = tid >> 5;

    // ---- Direct vectorized loads; noise first (gates the dependent chain) ----
    const float4* gn = reinterpret_cast<const float4*>(noise  + (size_t)b * MSTEPS)     + 2 * tid;
    const float4* gp = reinterpret_cast<const float4*>(pulses + (size_t)b * MSTEPS * 2) + 4 * tid;
    const float4 na = gn[0], nb = gn[1];
    const float4 pa = gp[0], pb = gp[1], pc = gp[2], pd = gp[3];

    // ---- Packed dual half-chains: lane0 = steps 0..3, lane1 = steps 4..7 ----
    const u64 H05 = f2pack(0.5f, 0.5f);
    u64 Cw[4], Cx[4], Cy[4], Cz[4];        // C2[i] = (L[i] | Hi[i])
    {
        u64 hx, hy, hz, uw, ux, uy, uz;
        hx = f2pack(pa.x, pc.x); hy = f2pack(pa.y, pc.y);
        hz = f2add(f2pack(na.x, nb.x), H05);
        stepq2(hx, hy, hz, Cw[0], Cx[0], Cy[0], Cz[0]);

        hx = f2pack(pa.z, pc.z); hy = f2pack(pa.w, pc.w);
        hz = f2add(f2pack(na.y, nb.y), H05);
        stepq2(hx, hy, hz, uw, ux, uy, uz);
        qmul2_negA(uw, ux, uy, uz, f2neg(ux), f2neg(uy), f2neg(uz),
                   Cw[0], Cx[0], Cy[0], Cz[0], Cw[1], Cx[1], Cy[1], Cz[1]);

        hx = f2pack(pb.x, pd.x); hy = f2pack(pb.y, pd.y);
        hz = f2add(f2pack(na.z, nb.z), H05);
        stepq2(hx, hy, hz, uw, ux, uy, uz);
        qmul2_negA(uw, ux, uy, uz, f2neg(ux), f2neg(uy), f2neg(uz),
                   Cw[1], Cx[1], Cy[1], Cz[1], Cw[2], Cx[2], Cy[2], Cz[2]);

        hx = f2pack(pb.z, pd.z); hy = f2pack(pb.w, pd.w);
        hz = f2add(f2pack(na.w, nb.w), H05);
        stepq2(hx, hy, hz, uw, ux, uy, uz);
        qmul2_negA(uw, ux, uy, uz, f2neg(ux), f2neg(uy), f2neg(uz),
                   Cw[2], Cx[2], Cy[2], Cz[2], Cw[3], Cx[3], Cy[3], Cz[3]);
    }

    // ---- L3 (lo) and Hi3 (hi); chunk total L7 = Hi3*L3 ----
    float4 L3q, Hi3;
    f2unpack(L3q.x, Hi3.x, Cw[3]); f2unpack(L3q.y, Hi3.y, Cx[3]);
    f2unpack(L3q.z, Hi3.z, Cy[3]); f2unpack(L3q.w, Hi3.w, Cz[3]);

    // ---- Warp-level inclusive scan of chunk products ----
    float4 v = qmul(Hi3, L3q);
#pragma unroll
    for (int off = 1; off < 32; off <<= 1) {
        float4 o = shfl_up_q(v, off);
        if (lane >= off) v = qmul(v, o);
    }
    if (lane == 31) wtot[wid] = v;
    __syncthreads();                 // the ONLY block barrier

    // ---- Every warp redundantly scans the 8 warp totals (3 rounds) ----
    float4 t = wtot[lane & 7];
#pragma unroll
    for (int off = 1; off < 8; off <<= 1) {
        float4 o = shfl_up_q(t, off);
        if (lane >= off && lane < 8) t = qmul(t, o);
    }
    float4 WE = shfl_q(t, (wid > 0) ? (wid - 1) : 0);
    if (wid == 0) WE = make_float4(1.f, 0.f, 0.f, 0.f);

    float4 TE = shfl_up_q(v, 1);
    if (lane == 0) TE = make_float4(1.f, 0.f, 0.f, 0.f);
    const float4 E = qmul(TE, WE);   // exclusive global prefix for this chunk
    const float4 F = qmul(L3q, E);   // prefix for the hi half: P(4+i)=Hi[i]*F

    // ---- Packed epilogue: P2(i) = C2[i] * (E|F) ----
    const u64 Bw  = f2pack(E.x, F.x), Bx = f2pack(E.y, F.y);
    const u64 By  = f2pack(E.z, F.z), Bz = f2pack(E.w, F.w);
    const u64 nBx = f2neg(Bx), nBy = f2neg(By), nBz = f2neg(Bz);
    const u64 M2  = f2pack(-2.f, -2.f), ONE = f2pack(1.f, 1.f);

    float4* srow = &sm4[tid * 13];
#pragma unroll
    for (int g = 0; g < 2; g++) {
        u64 S[2][6];
#pragma unroll
        for (int h = 0; h < 2; h++) {
            const int i = 2 * g + h;
            const u64 aw = Cw[i], ax = Cx[i], ay = Cy[i], az = Cz[i];
            u64 Pw = f2fma(az, nBz, f2fma(ay, nBy, f2fma(ax, nBx, f2mul(aw, Bw))));
            u64 Px = f2fma(az, nBy, f2fma(ay,  Bz, f2fma(ax,  Bw, f2mul(aw, Bx))));
            u64 Py = f2fma(az,  Bx, f2fma(ay,  Bw, f2fma(ax, nBz, f2mul(aw, By))));
            u64 Pz = f2fma(az,  Bw, f2fma(ay, nBx, f2fma(ax,  By, f2mul(aw, Bz))));
            u64 nPw = f2neg(Pw);
            u64 xz  = f2mul(Px, Pz);
            u64 s0  = f2fma(Pw, Py, xz);  s0 = f2add(s0, s0);
            u64 s1  = f2fma(nPw, Px, f2mul(Py, Pz)); s1 = f2add(s1, s1);
            u64 s2  = f2fma(f2fma(Py, Py, f2mul(Px, Px)), M2, ONE);
            u64 s3  = f2fma(f2fma(Pz, Pz, f2mul(Py, Py)), M2, ONE);
            u64 s4  = f2fma(Pw, Pz, f2mul(Px, Py)); s4 = f2add(s4, s4);
            u64 s5  = f2fma(nPw, Py, xz); s5 = f2add(s5, s5);
            S[h][0] = s0; S[h][1] = s1; S[h][2] = s2;
            S[h][3] = s3; S[h][4] = s4; S[h][5] = s5;
        }
        float a0,b0,a1,b1,a2,b2,a3,b3,a4,b4,a5,b5;
        float c0,d0,c1,d1,c2,d2,c3,d3,c4,d4,c5,d5;
        f2unpack(a0,b0,S[0][0]); f2unpack(a1,b1,S[0][1]); f2unpack(a2,b2,S[0][2]);
        f2unpack(a3,b3,S[0][3]); f2unpack(a4,b4,S[0][4]); f2unpack(a5,b5,S[0][5]);
        f2unpack(c0,d0,S[1][0]); f2unpack(c1,d1,S[1][1]); f2unpack(c2,d2,S[1][2]);
        f2unpack(c3,d3,S[1][3]); f2unpack(c4,d4,S[1][4]); f2unpack(c5,d5,S[1][5]);
        srow[3 * g + 0] = make_float4(a0, a1, a2, a3);
        srow[3 * g + 1] = make_float4(a4, a5, c0, c1);
        srow[3 * g + 2] = make_float4(c2, c3, c4, c5);
        srow[3 * g + 6] = make_float4(b0, b1, b2, b3);
        srow[3 * g + 7] = make_float4(b4, b5, d0, d1);
        srow[3 * g + 8] = make_float4(d2, d3, d4, d5);
    }
    __syncwarp();                    // producer = consumer = this warp

    // ---- Warp-local coalesced copy-out (evict-first stores) ----
    float4* og = reinterpret_cast<float4*>(out + (size_t)b * (MSTEPS * 6)) + 384 * wid;
    int r = lane / 12 + 32 * wid;
    int c = lane - (lane / 12) * 12;
#pragma unroll
    for (int k = 0; k < 12; k++) {
        stg_cs(&og[lane + 32 * k], sm4[r * 13 + c]);
        r += 2; c += 8;              // advance by 32 f4 = 2 rows + 8 cols
        if (c >= 12) { c -= 12; r += 1; }
    }
}

extern "C" void kernel_launch(void* const* d_in, const int* in_sizes, int n_in,
                              void* d_out, int out_size) {
    const float* noise  = (const float*)d_in[0];   // [512, 2048, 1]
    const float* pulses = (const float*)d_in[1];   // [512, 2048, 2]
    if (in_sizes[0] > in_sizes[1]) {               // defensive: order by size
        const float* t = noise; noise = pulses; pulses = t;
    }
    cudaFuncSetAttribute(qe_kernel,
                         cudaFuncAttributeMaxDynamicSharedMemorySize,
                         SMEM_BYTES);
    qe_kernel<<<BREAL, TPB, SMEM_BYTES>>>(noise, pulses, (float*)d_out);
}